// round 15
// baseline (speedup 1.0000x reference)
#include <cuda_runtime.h>
#include <stdint.h>

// Problem constants (DynamicNeuralGraph_57758720197073)
#define NN   256    // num neurons
#define IDIM 784    // input dim
#define HDIM 128    // hidden dim
#define BDIM 256    // batch
#define PCH  8      // number of edge chunks
#define LMAX 512    // max edges per chunk (E=4096 / 8)

// Scratch (no allocations allowed -> __device__ globals)
__device__ float g_A[PCH][NN * NN];      // chunk transfer matrices, column-major: [p][j*NN + i]
__device__ float g_c[NN];                // neuron coefficient vector
__device__ float g_beff[HDIM];           // effective bias
__device__ float g_weff[IDIM * HDIM];    // effective weight matrix

// ---------------------------------------------------------------------------
// K1 v3: build chunk transfer matrices.
// Reverse recurrence c[s] += w*c[t] per edge == row_s += w*row_t on identity,
// in reverse edge order. 64 CTAs x 32 threads = 8 chunks x 8 column-groups.
// Pairwise hazard-resolved chain (R10-proven). v3: edge metadata packed --
// (s*33, t*33) as 16-bit halves of ONE uint32, read as LDS.64 per pair along
// with an LDS.64 of the two weights: 6 scalar LDS -> 2 wide LDS per pair in
// an issue-bound loop.
// ---------------------------------------------------------------------------
__global__ void k_chunks(const int* __restrict__ eidx,
                         const float* __restrict__ ew, int E) {
    __shared__ float    rows[NN * 33];   // 32 columns + stride-33
    __shared__ uint32_t epk[LMAX + 2];   // packed (s*33 | t*33<<16)
    __shared__ float    ewv[LMAX + 2];

    const int p  = blockIdx.x >> 3;      // chunk id
    const int cg = blockIdx.x & 7;       // column group
    const int j  = threadIdx.x;          // 0..31 (one column per lane)
    const int jg = cg * 32 + j;          // global column

    // identity init for this CTA's 32 columns
    #pragma unroll 8
    for (int i = 0; i < NN; i++)
        rows[i * 33 + j] = (i == jg) ? 1.0f : 0.0f;

    int L  = (E + PCH - 1) / PCH;
    if (L > LMAX) L = LMAX;              // safety (E is 4096 for this problem)
    const int r0 = p * L;
    int cnt = E - r0;
    if (cnt > L) cnt = L;
    if (cnt < 0) cnt = 0;

    // stage this chunk's edges in REVERSE global order, packed
    for (int r = j; r < cnt; r += 32) {
        int k   = E - 1 - (r0 + r);
        uint32_t so = (uint32_t)(eidx[k] * 33);          // src offset (<8447)
        uint32_t to = (uint32_t)(eidx[E + k] * 33);      // tgt offset
        epk[r]  = so | (to << 16);
        ewv[r]  = ew[k];
    }
    if (j == 0) { epk[cnt] = 0; epk[cnt + 1] = 0; ewv[cnt] = 0.f; ewv[cnt + 1] = 0.f; }
    __syncthreads();

    // pairwise serial chain
    float* rj = rows + j;
    const int npair = cnt >> 1;
    for (int q = 0; q < npair; q++) {
        const uint2  pk = *(const uint2*)&epk[q * 2];    // LDS.64 (8B aligned)
        const float2 wv = *(const float2*)&ewv[q * 2];
        const int s0 = pk.x & 0xFFFF, t0 = pk.x >> 16;
        const int s1 = pk.y & 0xFFFF, t1 = pk.y >> 16;
        const float a0 = rj[t0];
        const float b0 = rj[s0];
        const float a1 = rj[t1];
        const float b1 = rj[s1];
        const float ns0 = fmaf(wv.x, a0, b0);
        const float ct1 = (t1 == s0) ? ns0 : a1;
        const float cs1 = (s1 == s0) ? ns0 : b1;
        const float ns1 = fmaf(wv.y, ct1, cs1);
        rj[s0] = ns0;
        rj[s1] = ns1;                    // same-addr case: cumulative value wins
    }
    if (cnt & 1) {                       // odd tail
        const uint32_t pk = epk[cnt - 1];
        const int s0 = pk & 0xFFFF, t0 = pk >> 16;
        rj[s0] = fmaf(ewv[cnt - 1], rj[t0], rj[s0]);
    }
    __syncthreads();

    // write out column-major g_A[p][jc*NN + i], coalesced over i
    float* out = g_A[p];
    #pragma unroll 4
    for (int jl = 0; jl < 32; jl++) {
        const int jc = cg * 32 + jl;
        #pragma unroll
        for (int ib = 0; ib < NN; ib += 32)
            out[jc * NN + ib + j] = rows[(ib + j) * 33 + jl];
    }
}

// ---------------------------------------------------------------------------
// K2 v3: combine. v = u; for p: v <- A_p v. Then c = v, beff = sum c[m]*b[m].
// One CTA, 1024 threads; depth-8 float4 ring with cross-p prefetch (loads of
// p+1 issue before p's barriers). v3: 2 barriers per p instead of 3 (ps and
// v are distinct arrays; the pre-ps-write barrier was redundant).
// ---------------------------------------------------------------------------
__global__ void __launch_bounds__(1024) k_combine(const float* __restrict__ bb) {
    __shared__ float v[NN];
    __shared__ float ps[16][NN];

    const int tid = threadIdx.x;
    if (tid < NN) v[tid] = 1.0f / (float)NN;   // u = mean functional

    const int i4  = tid & 63;    // row group (rows i4*4 .. i4*4+3)
    const int seg = tid >> 6;    // j segment (cols seg*16 .. +15)

    // base pointer for (p=0, jj=0) of this thread's tile
    const float* A0 = &g_A[0][0] + (size_t)(seg * 16) * NN + i4 * 4;
    #define A_LD(pp, jj) (*(const float4*)(A0 + (size_t)(pp) * (NN * NN) + (size_t)(jj) * NN))

    // depth-8 ring: prime with p=0, jj=0..7 (independent of v)
    float4 rbuf[8];
    #pragma unroll
    for (int q = 0; q < 8; q++) rbuf[q] = A_LD(0, q);

    __syncthreads();                     // v ready

    for (int p = 0; p < PCH; p++) {
        float ax = 0.f, ay = 0.f, az = 0.f, aw = 0.f;
        // consume jj=0..7, refill with jj=8..15 of same p
        #pragma unroll
        for (int q = 0; q < 8; q++) {
            const float vj = v[seg * 16 + q];
            const float4 a = rbuf[q];
            ax = fmaf(a.x, vj, ax);
            ay = fmaf(a.y, vj, ay);
            az = fmaf(a.z, vj, az);
            aw = fmaf(a.w, vj, aw);
            rbuf[q] = A_LD(p, 8 + q);
        }
        // consume jj=8..15, refill with NEXT matrix's jj=0..7 (clamped)
        const int pn = (p < PCH - 1) ? p + 1 : PCH - 1;
        #pragma unroll
        for (int q = 0; q < 8; q++) {
            const float vj = v[seg * 16 + 8 + q];
            const float4 a = rbuf[q];
            ax = fmaf(a.x, vj, ax);
            ay = fmaf(a.y, vj, ay);
            az = fmaf(a.z, vj, az);
            aw = fmaf(a.w, vj, aw);
            rbuf[q] = A_LD(pn, q);       // in flight across the barriers below
        }
        *(float4*)&ps[seg][i4 * 4] = make_float4(ax, ay, az, aw);
        __syncthreads();                 // all FMA-phase v reads + ps writes done
        if (tid < NN) {
            float sum = 0.f;
            #pragma unroll
            for (int sg = 0; sg < 16; sg++) sum += ps[sg][tid];
            v[tid] = sum;
        }
        __syncthreads();                 // v updated before next p reads it
    }
    #undef A_LD

    if (tid < NN) g_c[tid] = v[tid];

    // beff[h] = sum_m v[m] * b[m][h]
    const int h  = tid & 127;
    const int ms = tid >> 7;             // 0..7, each covers 32 m's
    float acc = 0.f;
    #pragma unroll 8
    for (int mm = 0; mm < 32; mm++) {
        const int m = ms * 32 + mm;
        acc = fmaf(v[m], bb[m * HDIM + h], acc);
    }
    ps[ms][h] = acc;
    __syncthreads();
    if (tid < HDIM) {
        float sum = 0.f;
        #pragma unroll
        for (int sg = 0; sg < 8; sg++) sum += ps[sg][tid];
        g_beff[tid] = sum;
    }
}

// ---------------------------------------------------------------------------
// K3: Weff[i][h] = sum_m c[m] * W[m][i][h].  Streams 103 MB once.
// 392 CTAs x 256 threads, CTA owns 2 rows; warp = (row-half, m-quarter);
// depth-8 named-register prefetch ring. UNCHANGED (measured-good, ~DRAM floor).
// ---------------------------------------------------------------------------
__global__ void __launch_bounds__(256) k_weff(const float* __restrict__ W) {
    __shared__ float c[NN];
    __shared__ float ps[8][HDIM];            // per-warp partial rows

    const int tid = threadIdx.x;             // 0..255
    if (tid < NN) c[tid] = g_c[tid];

    const int warp = tid >> 5;
    const int lane = tid & 31;
    const int il   = warp >> 2;              // row within CTA (0..1)
    const int mq   = warp & 3;               // m-quarter (0..3)
    const int i    = blockIdx.x * 2 + il;    // 0..783
    const int m0   = mq * 64;
    const float* base = W + (size_t)i * HDIM + lane * 4;

    // depth-8 prefetch ring over the 64 m's of this quarter (clamped)
    #define W_LD(kk) (*(const float4*)(base + (size_t)(m0 + (((kk) < 64) ? (kk) : 63)) * (IDIM * HDIM)))
    float4 buf[8];
    #pragma unroll
    for (int q = 0; q < 8; q++) buf[q] = W_LD(q);

    __syncthreads();                         // c ready

    float ax = 0.f, ay = 0.f, az = 0.f, aw = 0.f;
    #pragma unroll 1
    for (int k = 0; k < 56; k += 8) {
        #pragma unroll
        for (int q = 0; q < 8; q++) {
            const float cm = c[m0 + k + q];
            const float4 wv = buf[q];
            ax = fmaf(cm, wv.x, ax);
            ay = fmaf(cm, wv.y, ay);
            az = fmaf(cm, wv.z, az);
            aw = fmaf(cm, wv.w, aw);
            buf[q] = W_LD(k + q + 8);
        }
    }
    #pragma unroll
    for (int q = 0; q < 8; q++) {            // tail k = 56..63
        const float cm = c[m0 + 56 + q];
        const float4 wv = buf[q];
        ax = fmaf(cm, wv.x, ax);
        ay = fmaf(cm, wv.y, ay);
        az = fmaf(cm, wv.z, az);
        aw = fmaf(cm, wv.w, aw);
    }
    #undef W_LD

    *(float4*)&ps[warp][lane * 4] = make_float4(ax, ay, az, aw);
    __syncthreads();

    // 256 outputs (2 rows x 128 h), one per thread: sum 4 m-quarters
    {
        const int ol = tid >> 7;             // row 0..1
        const int h  = tid & 127;
        const float s = ps[ol * 4 + 0][h] + ps[ol * 4 + 1][h]
                      + ps[ol * 4 + 2][h] + ps[ol * 4 + 3][h];
        g_weff[(blockIdx.x * 2 + ol) * HDIM + h] = s;
    }
}

// ---------------------------------------------------------------------------
// K4 v7: out[b][h] = beff[h] + sum_i x[b][i] * Weff[i][h].
// v6 (ring-8) = 9.0us at issue 28.5%: per-warp ring window (~120 cyc) < L2
// latency (234). v7 deepens the ring to 16 so one warp self-covers L2
// latency (~240 cyc window). 128 CTAs x 512 threads x 2 batch rows,
// xs packed float2. ~87 regs/thread -> still 1 CTA/SM, no spill.
// ---------------------------------------------------------------------------
__global__ void __launch_bounds__(512) k_gemm(const float* __restrict__ x,
                                              float* __restrict__ out) {
    __shared__ float2 xs2[IDIM];             // (x[b0][i], x[b0+1][i]) packed
    __shared__ float  ps[16][2 * HDIM];      // 16 KB per-warp partials

    const int tid = threadIdx.x;             // 0..511
    const int b0  = blockIdx.x * 2;

    // stage 2 batch rows of x, packed per i
    for (int i = tid; i < IDIM; i += 512)
        xs2[i] = make_float2(x[b0 * IDIM + i], x[(b0 + 1) * IDIM + i]);

    const int warp = tid >> 5;               // i-parity 0..15
    const int lane = tid & 31;               // h-quad
    const float* wp = g_weff + lane * 4;

    // ring: iteration k covers i = warp + 16k, k = 0..48 (784 = 49*16)
    #define K_LD(kk) (*(const float4*)(wp + (warp + (((kk) < 49) ? (kk) : 48) * 16) * HDIM))
    float4 buf[16];
    #pragma unroll
    for (int q = 0; q < 16; q++) buf[q] = K_LD(q);

    __syncthreads();                         // xs2 ready

    float a0x=0.f,a0y=0.f,a0z=0.f,a0w=0.f;
    float a1x=0.f,a1y=0.f,a1z=0.f,a1w=0.f;

    #define CONSUME(kk, qq)                                              \
    {                                                                    \
        const int i = warp + (kk) * 16;                                  \
        const float4 wv = buf[qq];                                       \
        const float2 xv = xs2[i];                                        \
        a0x = fmaf(xv.x, wv.x, a0x); a0y = fmaf(xv.x, wv.y, a0y);        \
        a0z = fmaf(xv.x, wv.z, a0z); a0w = fmaf(xv.x, wv.w, a0w);        \
        a1x = fmaf(xv.y, wv.x, a1x); a1y = fmaf(xv.y, wv.y, a1y);        \
        a1z = fmaf(xv.y, wv.z, a1z); a1w = fmaf(xv.y, wv.w, a1w);        \
    }

    // main loop: k = 0..31 consumed, ring stays 16 deep
    #pragma unroll 1
    for (int k = 0; k < 32; k += 16) {
        #pragma unroll
        for (int q = 0; q < 16; q++) {
            CONSUME(k + q, q);
            buf[q] = K_LD(k + q + 16);
        }
    }
    // buf now holds k = 32..47; issue k=48's load, then drain
    float4 last = K_LD(48);
    #pragma unroll
    for (int q = 0; q < 16; q++) CONSUME(32 + q, q);
    {
        const int i = warp + 48 * 16;
        const float4 wv = last;
        const float2 xv = xs2[i];
        a0x = fmaf(xv.x, wv.x, a0x); a0y = fmaf(xv.x, wv.y, a0y);
        a0z = fmaf(xv.x, wv.z, a0z); a0w = fmaf(xv.x, wv.w, a0w);
        a1x = fmaf(xv.y, wv.x, a1x); a1y = fmaf(xv.y, wv.y, a1y);
        a1z = fmaf(xv.y, wv.z, a1z); a1w = fmaf(xv.y, wv.w, a1w);
    }
    #undef CONSUME
    #undef K_LD

    // per-warp partials -> smem
    *(float4*)&ps[warp][0 * HDIM + lane * 4] = make_float4(a0x, a0y, a0z, a0w);
    *(float4*)&ps[warp][1 * HDIM + lane * 4] = make_float4(a1x, a1y, a1z, a1w);
    __syncthreads();

    // reduce over 16 warps: 256 outputs, threads 0..255
    if (tid < 2 * HDIM) {
        float s = 0.f;
        #pragma unroll
        for (int wv = 0; wv < 16; wv++) s += ps[wv][tid];
        const int bl = tid >> 7;             // 0..1
        const int h  = tid & 127;
        out[(b0 + bl) * HDIM + h] = s + g_beff[h];
    }
}

// ---------------------------------------------------------------------------
// Inputs (metadata order): x (B,I) f32 | W (N,I,H) f32 | b (N,H) f32 |
// edge_index (2,E) i32 | edge_weights (E,) f32.  Output: (B,H) f32.
// ---------------------------------------------------------------------------
extern "C" void kernel_launch(void* const* d_in, const int* in_sizes, int n_in,
                              void* d_out, int out_size) {
    const float* x    = (const float*)d_in[0];
    const float* W    = (const float*)d_in[1];
    const float* b    = (const float*)d_in[2];
    const int*   eidx = (const int*)d_in[3];
    const float* ew   = (const float*)d_in[4];
    const int    E    = in_sizes[4];         // 4096

    k_chunks <<<64, 32>>>(eidx, ew, E);      // packed pairwise chunk matrices
    k_combine<<<1, 1024>>>(b);               // c vector + beff (ringed, 2-barrier)
    k_weff   <<<392, 256>>>(W);              // Weff = sum c[m] W[m]  (DRAM stream)
    k_gemm   <<<128, 512>>>(x, (float*)d_out);
}

// round 16
// speedup vs baseline: 1.3755x; 1.3755x over previous
#include <cuda_runtime.h>

// Problem constants (DynamicNeuralGraph_57758720197073)
#define NN   256    // num neurons
#define IDIM 784    // input dim
#define HDIM 128    // hidden dim
#define BDIM 256    // batch
#define PCH  8      // number of edge chunks
#define LMAX 512    // max edges per chunk (E=4096 / 8)

// Scratch (no allocations allowed -> __device__ globals)
__device__ float g_A[PCH][NN * NN];      // chunk transfer matrices, column-major: [p][j*NN + i]
__device__ float g_c[NN];                // neuron coefficient vector
__device__ float g_beff[HDIM];           // effective bias
__device__ float g_weff[IDIM * HDIM];    // effective weight matrix

// ---------------------------------------------------------------------------
// K1 (R14-exact, measured-good): build chunk transfer matrices.
// Reverse recurrence c[s] += w*c[t] per edge == row_s += w*row_t on identity,
// in reverse edge order. 64 CTAs x 32 threads = 8 chunks x 8 column-groups.
// Pairwise hazard-resolved chain: one 29-cyc LDS latency per 2 edges.
// ---------------------------------------------------------------------------
__global__ void k_chunks(const int* __restrict__ eidx,
                         const float* __restrict__ ew, int E) {
    __shared__ float rows[NN * 33];      // 32 columns + stride-33 (conflict-free transpose)
    __shared__ int   es[LMAX + 1];       // s*33 offsets
    __shared__ int   et[LMAX + 1];       // t*33 offsets
    __shared__ float ewv[LMAX + 1];

    const int p  = blockIdx.x >> 3;      // chunk id
    const int cg = blockIdx.x & 7;       // column group
    const int j  = threadIdx.x;          // 0..31 (one column per lane)
    const int jg = cg * 32 + j;          // global column

    // identity init for this CTA's 32 columns
    #pragma unroll 8
    for (int i = 0; i < NN; i++)
        rows[i * 33 + j] = (i == jg) ? 1.0f : 0.0f;

    int L  = (E + PCH - 1) / PCH;
    if (L > LMAX) L = LMAX;              // safety (E is 4096 for this problem)
    const int r0 = p * L;
    int cnt = E - r0;
    if (cnt > L) cnt = L;
    if (cnt < 0) cnt = 0;

    // stage this chunk's edges in REVERSE global order, as *33 offsets
    for (int r = j; r < cnt; r += 32) {
        int k   = E - 1 - (r0 + r);
        es[r]   = eidx[k] * 33;          // src offset
        et[r]   = eidx[E + k] * 33;      // tgt offset
        ewv[r]  = ew[k];
    }
    __syncthreads();

    // pairwise serial chain
    float* rj = rows + j;
    int r = 0;
    for (; r + 1 < cnt; r += 2) {
        const int   s0 = es[r],     t0 = et[r];
        const int   s1 = es[r + 1], t1 = et[r + 1];
        const float w0 = ewv[r],    w1 = ewv[r + 1];
        const float a0 = rj[t0];
        const float b0 = rj[s0];
        const float a1 = rj[t1];
        const float b1 = rj[s1];
        const float ns0 = fmaf(w0, a0, b0);
        const float ct1 = (t1 == s0) ? ns0 : a1;
        const float cs1 = (s1 == s0) ? ns0 : b1;
        const float ns1 = fmaf(w1, ct1, cs1);
        rj[s0] = ns0;
        rj[s1] = ns1;                    // same-addr case: cumulative value wins
    }
    if (r < cnt) {                       // odd tail
        const int   s0 = es[r], t0 = et[r];
        const float w0 = ewv[r];
        rj[s0] = fmaf(w0, rj[t0], rj[s0]);
    }
    __syncthreads();

    // write out column-major g_A[p][jc*NN + i], coalesced over i
    float* out = g_A[p];
    #pragma unroll 4
    for (int jl = 0; jl < 32; jl++) {
        const int jc = cg * 32 + jl;
        #pragma unroll
        for (int ib = 0; ib < NN; ib += 32)
            out[jc * NN + ib + j] = rows[(ib + j) * 33 + jl];
    }
}

// ---------------------------------------------------------------------------
// K2 (R14-exact, measured-good): combine. v = u; for p: v <- A_p v.
// Then c = v, beff = sum c[m]*b[m]. One CTA, 1024 threads; depth-8 float4
// ring with cross-p prefetch (loads of p+1 in flight across p's barriers).
// ---------------------------------------------------------------------------
__global__ void __launch_bounds__(1024) k_combine(const float* __restrict__ bb) {
    __shared__ float v[NN];
    __shared__ float ps[16][NN];

    const int tid = threadIdx.x;
    if (tid < NN) v[tid] = 1.0f / (float)NN;   // u = mean functional

    const int i4  = tid & 63;    // row group (rows i4*4 .. i4*4+3)
    const int seg = tid >> 6;    // j segment (cols seg*16 .. +15)

    // base pointer for (p=0, jj=0) of this thread's tile
    const float* A0 = &g_A[0][0] + (size_t)(seg * 16) * NN + i4 * 4;
    #define A_LD(pp, jj) (*(const float4*)(A0 + (size_t)(pp) * (NN * NN) + (size_t)(jj) * NN))

    // depth-8 ring: prime with p=0, jj=0..7 (independent of v)
    float4 rbuf[8];
    #pragma unroll
    for (int q = 0; q < 8; q++) rbuf[q] = A_LD(0, q);

    __syncthreads();                     // v ready

    for (int p = 0; p < PCH; p++) {
        float ax = 0.f, ay = 0.f, az = 0.f, aw = 0.f;
        // consume jj=0..7, refill with jj=8..15 of same p
        #pragma unroll
        for (int q = 0; q < 8; q++) {
            const float vj = v[seg * 16 + q];
            const float4 a = rbuf[q];
            ax = fmaf(a.x, vj, ax);
            ay = fmaf(a.y, vj, ay);
            az = fmaf(a.z, vj, az);
            aw = fmaf(a.w, vj, aw);
            rbuf[q] = A_LD(p, 8 + q);
        }
        // consume jj=8..15, refill with NEXT matrix's jj=0..7 (clamped)
        const int pn = (p < PCH - 1) ? p + 1 : PCH - 1;
        #pragma unroll
        for (int q = 0; q < 8; q++) {
            const float vj = v[seg * 16 + 8 + q];
            const float4 a = rbuf[q];
            ax = fmaf(a.x, vj, ax);
            ay = fmaf(a.y, vj, ay);
            az = fmaf(a.z, vj, az);
            aw = fmaf(a.w, vj, aw);
            rbuf[q] = A_LD(pn, q);       // in flight across the barriers below
        }
        __syncthreads();                 // all v reads done before overwrite
        *(float4*)&ps[seg][i4 * 4] = make_float4(ax, ay, az, aw);
        __syncthreads();
        if (tid < NN) {
            float sum = 0.f;
            #pragma unroll
            for (int sg = 0; sg < 16; sg++) sum += ps[sg][tid];
            v[tid] = sum;
        }
        __syncthreads();
    }
    #undef A_LD

    if (tid < NN) g_c[tid] = v[tid];

    // beff[h] = sum_m v[m] * b[m][h]
    const int h  = tid & 127;
    const int ms = tid >> 7;             // 0..7, each covers 32 m's
    float acc = 0.f;
    #pragma unroll 8
    for (int mm = 0; mm < 32; mm++) {
        const int m = ms * 32 + mm;
        acc = fmaf(v[m], bb[m * HDIM + h], acc);
    }
    ps[ms][h] = acc;
    __syncthreads();
    if (tid < HDIM) {
        float sum = 0.f;
        #pragma unroll
        for (int sg = 0; sg < 8; sg++) sum += ps[sg][tid];
        g_beff[tid] = sum;
    }
}

// ---------------------------------------------------------------------------
// K3: Weff[i][h] = sum_m c[m] * W[m][i][h].  Streams 103 MB once.
// 392 CTAs x 256 threads, CTA owns 2 rows; warp = (row-half, m-quarter);
// depth-8 named-register prefetch ring. UNCHANGED (measured-good, ~DRAM floor).
// ---------------------------------------------------------------------------
__global__ void __launch_bounds__(256) k_weff(const float* __restrict__ W) {
    __shared__ float c[NN];
    __shared__ float ps[8][HDIM];            // per-warp partial rows

    const int tid = threadIdx.x;             // 0..255
    if (tid < NN) c[tid] = g_c[tid];

    const int warp = tid >> 5;
    const int lane = tid & 31;
    const int il   = warp >> 2;              // row within CTA (0..1)
    const int mq   = warp & 3;               // m-quarter (0..3)
    const int i    = blockIdx.x * 2 + il;    // 0..783
    const int m0   = mq * 64;
    const float* base = W + (size_t)i * HDIM + lane * 4;

    // depth-8 prefetch ring over the 64 m's of this quarter (clamped)
    #define W_LD(kk) (*(const float4*)(base + (size_t)(m0 + (((kk) < 64) ? (kk) : 63)) * (IDIM * HDIM)))
    float4 buf[8];
    #pragma unroll
    for (int q = 0; q < 8; q++) buf[q] = W_LD(q);

    __syncthreads();                         // c ready

    float ax = 0.f, ay = 0.f, az = 0.f, aw = 0.f;
    #pragma unroll 1
    for (int k = 0; k < 56; k += 8) {
        #pragma unroll
        for (int q = 0; q < 8; q++) {
            const float cm = c[m0 + k + q];
            const float4 wv = buf[q];
            ax = fmaf(cm, wv.x, ax);
            ay = fmaf(cm, wv.y, ay);
            az = fmaf(cm, wv.z, az);
            aw = fmaf(cm, wv.w, aw);
            buf[q] = W_LD(k + q + 8);
        }
    }
    #pragma unroll
    for (int q = 0; q < 8; q++) {            // tail k = 56..63
        const float cm = c[m0 + 56 + q];
        const float4 wv = buf[q];
        ax = fmaf(cm, wv.x, ax);
        ay = fmaf(cm, wv.y, ay);
        az = fmaf(cm, wv.z, az);
        aw = fmaf(cm, wv.w, aw);
    }
    #undef W_LD

    *(float4*)&ps[warp][lane * 4] = make_float4(ax, ay, az, aw);
    __syncthreads();

    // 256 outputs (2 rows x 128 h), one per thread: sum 4 m-quarters
    {
        const int ol = tid >> 7;             // row 0..1
        const int h  = tid & 127;
        const float s = ps[ol * 4 + 0][h] + ps[ol * 4 + 1][h]
                      + ps[ol * 4 + 2][h] + ps[ol * 4 + 3][h];
        g_weff[(blockIdx.x * 2 + ol) * HDIM + h] = s;
    }
}

// ---------------------------------------------------------------------------
// K4 v8: out[b][h] = beff[h] + sum_i x[b][i] * Weff[i][h].
// R15 lesson: ring-16 traded regs for issue and lost. The real limiter at
// 128 CTAs x 512 thr was 1 CTA/SM -> 16 warps (25% occ cap). v8 keeps the
// measured-best ring-8 + float2 + 2 rows/CTA but with 1024 threads/CTA:
// 32 warps/SM (50% occ), i-stride 32, 25 iters/warp. xs2 is zero-padded to
// 800 so every warp runs a uniform trip count (weff address clamped in pad).
// ---------------------------------------------------------------------------
#define IPAD 800                             // 25 * 32
__global__ void __launch_bounds__(1024) k_gemm(const float* __restrict__ x,
                                               float* __restrict__ out) {
    __shared__ float2 xs2[IPAD];             // (x[b0][i], x[b0+1][i]), zero-padded
    __shared__ float  ps[32][2 * HDIM];      // 32 KB per-warp partials

    const int tid = threadIdx.x;             // 0..1023
    const int b0  = blockIdx.x * 2;

    // stage 2 batch rows of x, packed per i; zero the pad region
    for (int i = tid; i < IPAD; i += 1024)
        xs2[i] = (i < IDIM) ? make_float2(x[b0 * IDIM + i], x[(b0 + 1) * IDIM + i])
                            : make_float2(0.f, 0.f);

    const int warp = tid >> 5;               // i-parity 0..31
    const int lane = tid & 31;               // h-quad
    const float* wp = g_weff + lane * 4;

    // iteration k covers i = warp + 32k, k = 0..24; clamp address for pad i's
    #define K_LD(kk) (*(const float4*)(wp + ((warp + (kk) * 32 < IDIM) ? (warp + (kk) * 32) : (IDIM - 1)) * HDIM))
    float4 buf[8];
    #pragma unroll
    for (int q = 0; q < 8; q++) buf[q] = K_LD(q);

    __syncthreads();                         // xs2 ready

    float a0x=0.f,a0y=0.f,a0z=0.f,a0w=0.f;
    float a1x=0.f,a1y=0.f,a1z=0.f,a1w=0.f;

    #define CONSUME(kk, qq)                                              \
    {                                                                    \
        const int i = warp + (kk) * 32;                                  \
        const float4 wv = buf[qq];                                       \
        const float2 xv = xs2[i];                                        \
        a0x = fmaf(xv.x, wv.x, a0x); a0y = fmaf(xv.x, wv.y, a0y);        \
        a0z = fmaf(xv.x, wv.z, a0z); a0w = fmaf(xv.x, wv.w, a0w);        \
        a1x = fmaf(xv.y, wv.x, a1x); a1y = fmaf(xv.y, wv.y, a1y);        \
        a1z = fmaf(xv.y, wv.z, a1z); a1w = fmaf(xv.y, wv.w, a1w);        \
    }

    // consume k = 0..15, refilling k = 8..23
    #pragma unroll 1
    for (int k = 0; k < 16; k += 8) {
        #pragma unroll
        for (int q = 0; q < 8; q++) {
            CONSUME(k + q, q);
            buf[q] = K_LD(k + q + 8);
        }
    }
    // k = 24 load, then drain k = 16..23 and the last one
    float4 last = K_LD(24);
    #pragma unroll
    for (int q = 0; q < 8; q++) CONSUME(16 + q, q);
    {
        const int i = warp + 24 * 32;        // <= 799, pad-safe
        const float4 wv = last;
        const float2 xv = xs2[i];
        a0x = fmaf(xv.x, wv.x, a0x); a0y = fmaf(xv.x, wv.y, a0y);
        a0z = fmaf(xv.x, wv.z, a0z); a0w = fmaf(xv.x, wv.w, a0w);
        a1x = fmaf(xv.y, wv.x, a1x); a1y = fmaf(xv.y, wv.y, a1y);
        a1z = fmaf(xv.y, wv.z, a1z); a1w = fmaf(xv.y, wv.w, a1w);
    }
    #undef CONSUME
    #undef K_LD

    // per-warp partials -> smem
    *(float4*)&ps[warp][0 * HDIM + lane * 4] = make_float4(a0x, a0y, a0z, a0w);
    *(float4*)&ps[warp][1 * HDIM + lane * 4] = make_float4(a1x, a1y, a1z, a1w);
    __syncthreads();

    // reduce over 32 warps: 256 outputs, threads 0..255
    if (tid < 2 * HDIM) {
        float s = 0.f;
        #pragma unroll
        for (int wv = 0; wv < 32; wv++) s += ps[wv][tid];
        const int bl = tid >> 7;             // 0..1
        const int h  = tid & 127;
        out[(b0 + bl) * HDIM + h] = s + g_beff[h];
    }
}

// ---------------------------------------------------------------------------
// Inputs (metadata order): x (B,I) f32 | W (N,I,H) f32 | b (N,H) f32 |
// edge_index (2,E) i32 | edge_weights (E,) f32.  Output: (B,H) f32.
// ---------------------------------------------------------------------------
extern "C" void kernel_launch(void* const* d_in, const int* in_sizes, int n_in,
                              void* d_out, int out_size) {
    const float* x    = (const float*)d_in[0];
    const float* W    = (const float*)d_in[1];
    const float* b    = (const float*)d_in[2];
    const int*   eidx = (const int*)d_in[3];
    const float* ew   = (const float*)d_in[4];
    const int    E    = in_sizes[4];         // 4096

    k_chunks <<<64, 32>>>(eidx, ew, E);      // pairwise chunk transfer matrices
    k_combine<<<1, 1024>>>(b);               // c vector + beff (ringed matvecs)
    k_weff   <<<392, 256>>>(W);              // Weff = sum c[m] W[m]  (DRAM stream)
    k_gemm   <<<128, 1024>>>(x, (float*)d_out);
}

// round 17
// speedup vs baseline: 1.5594x; 1.1337x over previous
#include <cuda_runtime.h>

// Problem constants (DynamicNeuralGraph_57758720197073)
#define NN   256    // num neurons
#define IDIM 784    // input dim
#define HDIM 128    // hidden dim
#define BDIM 256    // batch
#define PCH  8      // number of edge chunks
#define LMAX 512    // max edges per chunk (E=4096 / 8)

// W size in float4s: 256*784*128/4
#define W_F4_TOTAL  6422528
// chunks-phase prefetch: 448 CTAs * 256 thr * 25 iters = 2,867,200 float4 (~45%)
#define PF1_CTAS    448
#define PF1_ITERS   25
#define PF1_STRIDE  (PF1_CTAS * 256)         // 114688
#define PF1_F4      (PF1_STRIDE * PF1_ITERS) // 2867200
// combine-phase prefetch: 147 CTAs * 1024 thr * 24 iters covers the rest
#define PF2_CTAS    147
#define PF2_ITERS   24
#define PF2_STRIDE  (PF2_CTAS * 1024)        // 150528

// Scratch (no allocations allowed -> __device__ globals)
__device__ float g_A[PCH][NN * NN];      // chunk transfer matrices, column-major: [p][j*NN + i]
__device__ float g_c[NN];                // neuron coefficient vector
__device__ float g_beff[HDIM];           // effective bias
__device__ float g_weff[IDIM * HDIM];    // effective weight matrix
__device__ float g_sink[16384];          // prefetch sums (anti-DCE; deterministic)

// warp-reduce a float4 sum and write one value per warp (keeps loads alive)
static __device__ __forceinline__ void sink_write(float4 acc, int blk, int warp, int lane) {
    float s = acc.x + acc.y + acc.z + acc.w;
    #pragma unroll
    for (int o = 16; o > 0; o >>= 1) s += __shfl_xor_sync(0xFFFFFFFFu, s, o);
    if (lane == 0) g_sink[(blk * 32 + warp) & 16383] = s;
}

// ---------------------------------------------------------------------------
// K1 v4: blocks 0..63 build chunk transfer matrices (R14-proven pairwise
// chain, now with 256 threads for the parallel phases); blocks 64..511
// stream the FIRST ~45% of W through L2 (prefetch for k_weff) using the
// otherwise-idle SMs and DRAM bandwidth under the serial-chain phase.
// ---------------------------------------------------------------------------
__global__ void __launch_bounds__(256)
k_chunks(const int* __restrict__ eidx, const float* __restrict__ ew, int E,
         const float* __restrict__ W) {
    // ---- prefetch blocks ----
    if (blockIdx.x >= 64) {
        const int tid  = threadIdx.x;
        const int pfid = blockIdx.x - 64;        // 0..447
        const float4* W4 = (const float4*)W;
        const size_t base = (size_t)pfid * 256 + tid;
        float4 acc = make_float4(0.f, 0.f, 0.f, 0.f);
        #pragma unroll 5
        for (int it = 0; it < PF1_ITERS; it++) {
            const float4 v = W4[base + (size_t)it * PF1_STRIDE];
            acc.x += v.x; acc.y += v.y; acc.z += v.z; acc.w += v.w;
        }
        sink_write(acc, blockIdx.x, tid >> 5, tid & 31);
        return;
    }

    __shared__ float rows[NN * 33];      // 32 columns + stride-33 (conflict-free transpose)
    __shared__ int   es[LMAX + 1];       // s*33 offsets
    __shared__ int   et[LMAX + 1];       // t*33 offsets
    __shared__ float ewv[LMAX + 1];

    const int tid = threadIdx.x;         // 0..255
    const int p   = blockIdx.x >> 3;     // chunk id
    const int cg  = blockIdx.x & 7;      // column group

    // identity init for this CTA's 32 columns (all 256 threads)
    #pragma unroll
    for (int v = tid; v < NN * 32; v += 256) {
        const int i = v >> 5;
        const int j = v & 31;
        rows[i * 33 + j] = (i == cg * 32 + j) ? 1.0f : 0.0f;
    }

    int L  = (E + PCH - 1) / PCH;
    if (L > LMAX) L = LMAX;              // safety (E is 4096 for this problem)
    const int r0 = p * L;
    int cnt = E - r0;
    if (cnt > L) cnt = L;
    if (cnt < 0) cnt = 0;

    // stage this chunk's edges in REVERSE global order, as *33 offsets
    for (int r = tid; r < cnt; r += 256) {
        int k   = E - 1 - (r0 + r);
        es[r]   = eidx[k] * 33;          // src offset
        et[r]   = eidx[E + k] * 33;      // tgt offset
        ewv[r]  = ew[k];
    }
    __syncthreads();

    // pairwise hazard-resolved serial chain (threads 0..31; lane = column j)
    if (tid < 32) {
        float* rj = rows + tid;
        int r = 0;
        for (; r + 1 < cnt; r += 2) {
            const int   s0 = es[r],     t0 = et[r];
            const int   s1 = es[r + 1], t1 = et[r + 1];
            const float w0 = ewv[r],    w1 = ewv[r + 1];
            const float a0 = rj[t0];
            const float b0 = rj[s0];
            const float a1 = rj[t1];
            const float b1 = rj[s1];
            const float ns0 = fmaf(w0, a0, b0);
            const float ct1 = (t1 == s0) ? ns0 : a1;
            const float cs1 = (s1 == s0) ? ns0 : b1;
            const float ns1 = fmaf(w1, ct1, cs1);
            rj[s0] = ns0;
            rj[s1] = ns1;                // same-addr case: cumulative value wins
        }
        if (r < cnt) {                   // odd tail
            const int   s0 = es[r], t0 = et[r];
            const float w0 = ewv[r];
            rj[s0] = fmaf(w0, rj[t0], rj[s0]);
        }
    }
    __syncthreads();

    // write out column-major g_A[p][jc*NN + i], coalesced over i (256 thr)
    {
        float* out = g_A[p];
        #pragma unroll
        for (int v = tid; v < 32 * NN; v += 256) {
            const int i  = v & 255;
            const int jl = v >> 8;       // 0..31
            out[(cg * 32 + jl) * NN + i] = rows[i * 33 + jl];
        }
    }
}

// ---------------------------------------------------------------------------
// K2 v4: block 0 = combine (R14-proven depth-8 ring with cross-p prefetch);
// blocks 1..147 stream the REMAINING ~55% of W through L2 under it.
// ---------------------------------------------------------------------------
__global__ void __launch_bounds__(1024)
k_combine(const float* __restrict__ bb, const float* __restrict__ W) {
    // ---- prefetch blocks ----
    if (blockIdx.x > 0) {
        const int tid = threadIdx.x;
        const float4* W4 = (const float4*)W;
        const size_t base = (size_t)PF1_F4 + (size_t)(blockIdx.x - 1) * 1024 + tid;
        float4 acc = make_float4(0.f, 0.f, 0.f, 0.f);
        #pragma unroll 4
        for (int it = 0; it < PF2_ITERS; it++) {
            const size_t idx = base + (size_t)it * PF2_STRIDE;
            if (idx < W_F4_TOTAL) {
                const float4 v = W4[idx];
                acc.x += v.x; acc.y += v.y; acc.z += v.z; acc.w += v.w;
            }
        }
        sink_write(acc, blockIdx.x, tid >> 5, tid & 31);
        return;
    }

    __shared__ float v[NN];
    __shared__ float ps[16][NN];

    const int tid = threadIdx.x;
    if (tid < NN) v[tid] = 1.0f / (float)NN;   // u = mean functional

    const int i4  = tid & 63;    // row group (rows i4*4 .. i4*4+3)
    const int seg = tid >> 6;    // j segment (cols seg*16 .. +15)

    // base pointer for (p=0, jj=0) of this thread's tile
    const float* A0 = &g_A[0][0] + (size_t)(seg * 16) * NN + i4 * 4;
    #define A_LD(pp, jj) (*(const float4*)(A0 + (size_t)(pp) * (NN * NN) + (size_t)(jj) * NN))

    // depth-8 ring: prime with p=0, jj=0..7 (independent of v)
    float4 rbuf[8];
    #pragma unroll
    for (int q = 0; q < 8; q++) rbuf[q] = A_LD(0, q);

    __syncthreads();                     // v ready

    for (int p = 0; p < PCH; p++) {
        float ax = 0.f, ay = 0.f, az = 0.f, aw = 0.f;
        // consume jj=0..7, refill with jj=8..15 of same p
        #pragma unroll
        for (int q = 0; q < 8; q++) {
            const float vj = v[seg * 16 + q];
            const float4 a = rbuf[q];
            ax = fmaf(a.x, vj, ax);
            ay = fmaf(a.y, vj, ay);
            az = fmaf(a.z, vj, az);
            aw = fmaf(a.w, vj, aw);
            rbuf[q] = A_LD(p, 8 + q);
        }
        // consume jj=8..15, refill with NEXT matrix's jj=0..7 (clamped)
        const int pn = (p < PCH - 1) ? p + 1 : PCH - 1;
        #pragma unroll
        for (int q = 0; q < 8; q++) {
            const float vj = v[seg * 16 + 8 + q];
            const float4 a = rbuf[q];
            ax = fmaf(a.x, vj, ax);
            ay = fmaf(a.y, vj, ay);
            az = fmaf(a.z, vj, az);
            aw = fmaf(a.w, vj, aw);
            rbuf[q] = A_LD(pn, q);       // in flight across the barriers below
        }
        __syncthreads();                 // all v reads done before overwrite
        *(float4*)&ps[seg][i4 * 4] = make_float4(ax, ay, az, aw);
        __syncthreads();
        if (tid < NN) {
            float sum = 0.f;
            #pragma unroll
            for (int sg = 0; sg < 16; sg++) sum += ps[sg][tid];
            v[tid] = sum;
        }
        __syncthreads();
    }
    #undef A_LD

    if (tid < NN) g_c[tid] = v[tid];

    // beff[h] = sum_m v[m] * b[m][h]
    const int h  = tid & 127;
    const int ms = tid >> 7;             // 0..7, each covers 32 m's
    float acc = 0.f;
    #pragma unroll 8
    for (int mm = 0; mm < 32; mm++) {
        const int m = ms * 32 + mm;
        acc = fmaf(v[m], bb[m * HDIM + h], acc);
    }
    ps[ms][h] = acc;
    __syncthreads();
    if (tid < HDIM) {
        float sum = 0.f;
        #pragma unroll
        for (int sg = 0; sg < 8; sg++) sum += ps[sg][tid];
        g_beff[tid] = sum;
    }
}

// ---------------------------------------------------------------------------
// K3: Weff[i][h] = sum_m c[m] * W[m][i][h].  W is now largely L2-resident
// (prefetched under k_chunks/k_combine). 392 CTAs x 256 threads; depth-8
// named-register prefetch ring. Code UNCHANGED (measured-good).
// ---------------------------------------------------------------------------
__global__ void __launch_bounds__(256) k_weff(const float* __restrict__ W) {
    __shared__ float c[NN];
    __shared__ float ps[8][HDIM];            // per-warp partial rows

    const int tid = threadIdx.x;             // 0..255
    if (tid < NN) c[tid] = g_c[tid];

    const int warp = tid >> 5;
    const int lane = tid & 31;
    const int il   = warp >> 2;              // row within CTA (0..1)
    const int mq   = warp & 3;               // m-quarter (0..3)
    const int i    = blockIdx.x * 2 + il;    // 0..783
    const int m0   = mq * 64;
    const float* base = W + (size_t)i * HDIM + lane * 4;

    // depth-8 prefetch ring over the 64 m's of this quarter (clamped)
    #define W_LD(kk) (*(const float4*)(base + (size_t)(m0 + (((kk) < 64) ? (kk) : 63)) * (IDIM * HDIM)))
    float4 buf[8];
    #pragma unroll
    for (int q = 0; q < 8; q++) buf[q] = W_LD(q);

    __syncthreads();                         // c ready

    float ax = 0.f, ay = 0.f, az = 0.f, aw = 0.f;
    #pragma unroll 1
    for (int k = 0; k < 56; k += 8) {
        #pragma unroll
        for (int q = 0; q < 8; q++) {
            const float cm = c[m0 + k + q];
            const float4 wv = buf[q];
            ax = fmaf(cm, wv.x, ax);
            ay = fmaf(cm, wv.y, ay);
            az = fmaf(cm, wv.z, az);
            aw = fmaf(cm, wv.w, aw);
            buf[q] = W_LD(k + q + 8);
        }
    }
    #pragma unroll
    for (int q = 0; q < 8; q++) {            // tail k = 56..63
        const float cm = c[m0 + 56 + q];
        const float4 wv = buf[q];
        ax = fmaf(cm, wv.x, ax);
        ay = fmaf(cm, wv.y, ay);
        az = fmaf(cm, wv.z, az);
        aw = fmaf(cm, wv.w, aw);
    }
    #undef W_LD

    *(float4*)&ps[warp][lane * 4] = make_float4(ax, ay, az, aw);
    __syncthreads();

    // 256 outputs (2 rows x 128 h), one per thread: sum 4 m-quarters
    {
        const int ol = tid >> 7;             // row 0..1
        const int h  = tid & 127;
        const float s = ps[ol * 4 + 0][h] + ps[ol * 4 + 1][h]
                      + ps[ol * 4 + 2][h] + ps[ol * 4 + 3][h];
        g_weff[(blockIdx.x * 2 + ol) * HDIM + h] = s;
    }
}

// ---------------------------------------------------------------------------
// K4 v8 (R16-exact, measured 7.6us): out[b][h] = beff[h] + sum_i x[b][i]*Weff[i][h].
// 128 CTAs x 1024 threads x 2 batch rows, ring-8, float2 xs, 32 warps/SM.
// ---------------------------------------------------------------------------
#define IPAD 800                             // 25 * 32
__global__ void __launch_bounds__(1024) k_gemm(const float* __restrict__ x,
                                               float* __restrict__ out) {
    __shared__ float2 xs2[IPAD];             // (x[b0][i], x[b0+1][i]), zero-padded
    __shared__ float  ps[32][2 * HDIM];      // 32 KB per-warp partials

    const int tid = threadIdx.x;             // 0..1023
    const int b0  = blockIdx.x * 2;

    // stage 2 batch rows of x, packed per i; zero the pad region
    for (int i = tid; i < IPAD; i += 1024)
        xs2[i] = (i < IDIM) ? make_float2(x[b0 * IDIM + i], x[(b0 + 1) * IDIM + i])
                            : make_float2(0.f, 0.f);

    const int warp = tid >> 5;               // i-parity 0..31
    const int lane = tid & 31;               // h-quad
    const float* wp = g_weff + lane * 4;

    // iteration k covers i = warp + 32k, k = 0..24; clamp address for pad i's
    #define K_LD(kk) (*(const float4*)(wp + ((warp + (kk) * 32 < IDIM) ? (warp + (kk) * 32) : (IDIM - 1)) * HDIM))
    float4 buf[8];
    #pragma unroll
    for (int q = 0; q < 8; q++) buf[q] = K_LD(q);

    __syncthreads();                         // xs2 ready

    float a0x=0.f,a0y=0.f,a0z=0.f,a0w=0.f;
    float a1x=0.f,a1y=0.f,a1z=0.f,a1w=0.f;

    #define CONSUME(kk, qq)                                              \
    {                                                                    \
        const int i = warp + (kk) * 32;                                  \
        const float4 wv = buf[qq];                                       \
        const float2 xv = xs2[i];                                        \
        a0x = fmaf(xv.x, wv.x, a0x); a0y = fmaf(xv.x, wv.y, a0y);        \
        a0z = fmaf(xv.x, wv.z, a0z); a0w = fmaf(xv.x, wv.w, a0w);        \
        a1x = fmaf(xv.y, wv.x, a1x); a1y = fmaf(xv.y, wv.y, a1y);        \
        a1z = fmaf(xv.y, wv.z, a1z); a1w = fmaf(xv.y, wv.w, a1w);        \
    }

    // consume k = 0..15, refilling k = 8..23
    #pragma unroll 1
    for (int k = 0; k < 16; k += 8) {
        #pragma unroll
        for (int q = 0; q < 8; q++) {
            CONSUME(k + q, q);
            buf[q] = K_LD(k + q + 8);
        }
    }
    // k = 24 load, then drain k = 16..23 and the last one
    float4 last = K_LD(24);
    #pragma unroll
    for (int q = 0; q < 8; q++) CONSUME(16 + q, q);
    {
        const int i = warp + 24 * 32;        // <= 799, pad-safe
        const float4 wv = last;
        const float2 xv = xs2[i];
        a0x = fmaf(xv.x, wv.x, a0x); a0y = fmaf(xv.x, wv.y, a0y);
        a0z = fmaf(xv.x, wv.z, a0z); a0w = fmaf(xv.x, wv.w, a0w);
        a1x = fmaf(xv.y, wv.x, a1x); a1y = fmaf(xv.y, wv.y, a1y);
        a1z = fmaf(xv.y, wv.z, a1z); a1w = fmaf(xv.y, wv.w, a1w);
    }
    #undef CONSUME
    #undef K_LD

    // per-warp partials -> smem
    *(float4*)&ps[warp][0 * HDIM + lane * 4] = make_float4(a0x, a0y, a0z, a0w);
    *(float4*)&ps[warp][1 * HDIM + lane * 4] = make_float4(a1x, a1y, a1z, a1w);
    __syncthreads();

    // reduce over 32 warps: 256 outputs, threads 0..255
    if (tid < 2 * HDIM) {
        float s = 0.f;
        #pragma unroll
        for (int wv = 0; wv < 32; wv++) s += ps[wv][tid];
        const int bl = tid >> 7;             // 0..1
        const int h  = tid & 127;
        out[(b0 + bl) * HDIM + h] = s + g_beff[h];
    }
}

// ---------------------------------------------------------------------------
// Inputs (metadata order): x (B,I) f32 | W (N,I,H) f32 | b (N,H) f32 |
// edge_index (2,E) i32 | edge_weights (E,) f32.  Output: (B,H) f32.
// ---------------------------------------------------------------------------
extern "C" void kernel_launch(void* const* d_in, const int* in_sizes, int n_in,
                              void* d_out, int out_size) {
    const float* x    = (const float*)d_in[0];
    const float* W    = (const float*)d_in[1];
    const float* b    = (const float*)d_in[2];
    const int*   eidx = (const int*)d_in[3];
    const float* ew   = (const float*)d_in[4];
    const int    E    = in_sizes[4];         // 4096

    k_chunks <<<64 + PF1_CTAS, 256>>>(eidx, ew, E, W); // chain + W L2-prefetch (45%)
    k_combine<<<1 + PF2_CTAS, 1024>>>(b, W);           // combine + W L2-prefetch (55%)
    k_weff   <<<392, 256>>>(W);                        // Weff = sum c[m] W[m] (L2-hot)
    k_gemm   <<<128, 1024>>>(x, (float*)d_out);
}